// round 15
// baseline (speedup 1.0000x reference)
#include <cuda_runtime.h>
#include <cuda_fp16.h>
#include <cstdint>

#define THREADS 384
#define TB 8
#define NJ 12
#define DM 128
#define NH 4
#define HD 32
#define MR 96              // valid rows per CTA
#define PBR 16             // padded rows per batch

#define TSTR 136           // fp16 tile stride (halves)
#define QSTR 200           // fp16 QKV stride (halves), 2 heads

// smem byte offsets
#define OFF_X    0                          // 96 x 136 h  = 26112 (X, later Wo rows 0..95)
#define OFF_W    26112                      // 192 x 136 h = 52224 (W pass / QKV overlay / Wo rows 96..127)
#define OFF_AO   78336                      // 96 x 136 h  = 26112
#define OFF_BQ   104448
#define OFF_BK   104960
#define OFF_BV   105472
#define OFF_BO   105984
#define OFF_ADJ  106496                     // 144 f32
#define OFF_KM   107072                     // 96 f32
#define SMEM_BYTES 107520

// pre-converted fp16 weights
__device__ __half gWqkv[3 * DM * DM];       // [Wq|Wk|Wv] stacked: sub*16384 + row*128 + col
__device__ __half gWo[DM * DM];

__device__ __forceinline__ uint2 f4_to_h4(float4 v) {
    __half2 a = __floats2half2_rn(v.x, v.y);
    __half2 b = __floats2half2_rn(v.z, v.w);
    uint2 r;
    r.x = *(uint32_t*)&a; r.y = *(uint32_t*)&b;
    return r;
}

__global__ void convert_weights(const float* __restrict__ Wq, const float* __restrict__ Wk,
                                const float* __restrict__ Wv, const float* __restrict__ Wo) {
    int i = blockIdx.x * 256 + threadIdx.x;        // 0..4095
    *(uint2*)(gWqkv + 0*16384 + i*4) = f4_to_h4(((const float4*)Wq)[i]);
    *(uint2*)(gWqkv + 1*16384 + i*4) = f4_to_h4(((const float4*)Wk)[i]);
    *(uint2*)(gWqkv + 2*16384 + i*4) = f4_to_h4(((const float4*)Wv)[i]);
    *(uint2*)(gWo + i*4)             = f4_to_h4(((const float4*)Wo)[i]);
}

__device__ __forceinline__ void ldsm_x4(uint32_t* r, uint32_t addr) {
    asm volatile("ldmatrix.sync.aligned.m8n8.x4.shared.b16 {%0,%1,%2,%3}, [%4];"
        : "=r"(r[0]), "=r"(r[1]), "=r"(r[2]), "=r"(r[3]) : "r"(addr));
}
__device__ __forceinline__ void ldsm_x4t(uint32_t* r, uint32_t addr) {
    asm volatile("ldmatrix.sync.aligned.m8n8.x4.trans.shared.b16 {%0,%1,%2,%3}, [%4];"
        : "=r"(r[0]), "=r"(r[1]), "=r"(r[2]), "=r"(r[3]) : "r"(addr));
}
__device__ __forceinline__ void mma16(float* d, const uint32_t* a, const uint32_t* b) {
    asm volatile(
        "mma.sync.aligned.m16n8k16.row.col.f32.f16.f16.f32 "
        "{%0,%1,%2,%3}, {%4,%5,%6,%7}, {%8,%9}, {%0,%1,%2,%3};"
        : "+f"(d[0]), "+f"(d[1]), "+f"(d[2]), "+f"(d[3])
        : "r"(a[0]), "r"(a[1]), "r"(a[2]), "r"(a[3]), "r"(b[0]), "r"(b[1]));
}
__device__ __forceinline__ uint32_t h2u(__half2 h) { return *(uint32_t*)&h; }

__device__ __forceinline__ void cpa16(uint32_t saddr, const void* gptr) {
    asm volatile("cp.async.cg.shared.global [%0], [%1], 16;"
        :: "r"(saddr), "l"(__cvta_generic_to_global(gptr)) : "memory");
}
__device__ __forceinline__ void cp_commit() {
    asm volatile("cp.async.commit_group;" ::: "memory");
}
__device__ __forceinline__ void cp_wait0() {
    asm volatile("cp.async.wait_group 0;" ::: "memory");
}

__global__ void __launch_bounds__(THREADS, 2)
cross_joint_attn_kernel(
    const float* __restrict__ x, const float* __restrict__ vis,
    const float* __restrict__ bq, const float* __restrict__ bk,
    const float* __restrict__ bv, const float* __restrict__ bo,
    const float* __restrict__ bias_scale, const float* __restrict__ adj,
    float* __restrict__ out)
{
    extern __shared__ __align__(16) char smc[];
    __half* Xh  = (__half*)(smc + OFF_X);
    __half* QKV = (__half*)(smc + OFF_W);     // overlay on W
    __half* AOh = (__half*)(smc + OFF_AO);
    float* bqs  = (float*)(smc + OFF_BQ);
    float* bks  = (float*)(smc + OFF_BK);
    float* bvs  = (float*)(smc + OFF_BV);
    float* bos  = (float*)(smc + OFF_BO);
    float* adjb = (float*)(smc + OFF_ADJ);
    float* kmsk = (float*)(smc + OFF_KM);

    const int tid  = threadIdx.x;
    const int lane = tid & 31;
    const int warp = tid >> 5;
    const int cta  = blockIdx.x;
    const int gid  = lane >> 2;
    const int tig  = lane & 3;

    const uint32_t sb    = (uint32_t)__cvta_generic_to_shared(smc);
    const uint32_t sbX   = sb + OFF_X;
    const uint32_t sbW   = sb + OFF_W;
    const uint32_t sbQKV = sb + OFF_W;
    const uint32_t sbAO  = sb + OFF_AO;

    // ---- stage W pass 0 (heads 0,1) via cp.async, then X (fp32->fp16) ----
    #pragma unroll
    for (int j = 0; j < 8; j++) {
        int i = tid + j * THREADS;                 // < 3072 uint4
        int row = i >> 4, c = (i & 15) * 8;
        int hh  = row >= 96;
        int sub = (row - hh * 96) >> 5;            // 0=Wq 1=Wk 2=Wv
        cpa16(sbW + (uint32_t)(row * TSTR) * 2 + c * 2,
              gWqkv + sub * 16384 + (hh * HD + (row & 31)) * DM + c);
    }
    cp_commit();
    {
        const float4* xg = (const float4*)(x + (size_t)cta * MR * DM);
        #pragma unroll
        for (int j = 0; j < 8; j++) {
            int i = tid + j * THREADS;             // < 3072
            int row = i >> 5, kk = (i & 31) * 4;
            *(uint2*)(Xh + row * TSTR + kk) = f4_to_h4(xg[i]);
        }
    }
    if (tid < DM) {
        bqs[tid] = bq[tid]; bks[tid] = bk[tid];
        bvs[tid] = bv[tid]; bos[tid] = bo[tid];
    }
    if (tid < NJ * NJ) adjb[tid] = adj[tid] * bias_scale[0];
    if (tid < MR)      kmsk[tid] = -10.0f * (1.0f - vis[(size_t)cta * MR + tid]);
    cp_wait0();
    __syncthreads();

    // GEMM1 tiling: 12 warps, mg2 (48 rows) x ng6 (32 cols)
    const int mg = warp / 6, ng = warp - mg * 6;
    uint32_t aaddr[3], baddr[2];
    #pragma unroll
    for (int i = 0; i < 3; i++)
        aaddr[i] = sbX + (uint32_t)((mg * 48 + i * 16 + (lane & 15)) * TSTR) * 2
                       + ((lane >> 4) * 16);
    #pragma unroll
    for (int j = 0; j < 2; j++)
        baddr[j] = sbW + (uint32_t)((ng * 32 + j * 16 + (lane & 7) + ((lane >> 4) * 8)) * TSTR) * 2
                       + (((lane >> 3) & 1) * 16);

    const float QSCALE = 0.17677669529663687f;

    for (int p = 0; p < 2; ++p) {
        // ===== GEMM1: QKV(96x192) = X @ [Wq|Wk|Wv]_{2p,2p+1}^T =====
        float acc[3][4][4];
        #pragma unroll
        for (int i = 0; i < 3; i++)
            #pragma unroll
            for (int j = 0; j < 4; j++)
                #pragma unroll
                for (int r = 0; r < 4; r++) acc[i][j][r] = 0.0f;

        #pragma unroll
        for (int ks = 0; ks < 8; ks++) {
            uint32_t a[3][4], b[2][4];
            #pragma unroll
            for (int i = 0; i < 3; i++) ldsm_x4(a[i], aaddr[i] + ks * 32);
            #pragma unroll
            for (int j = 0; j < 2; j++) ldsm_x4(b[j], baddr[j] + ks * 32);
            #pragma unroll
            for (int i = 0; i < 3; i++)
                #pragma unroll
                for (int j = 0; j < 2; j++) {
                    mma16(acc[i][2*j],   a[i], b[j]);
                    mma16(acc[i][2*j+1], a[i], b[j] + 2);
                }
        }
        __syncthreads();   // all W (and X, for p=1) reads done before overlay writes

        // bias (+Q prescale) + scatter to batch-padded fp16 QKV (overlay on W)
        #pragma unroll
        for (int i = 0; i < 3; i++) {
            int r0 = mg * 48 + i * 16 + gid;
            int pr0 = (r0 / NJ) * PBR + (r0 % NJ);
            int r1 = r0 + 8;
            int pr1 = (r1 / NJ) * PBR + (r1 % NJ);
            #pragma unroll
            for (int j = 0; j < 4; j++) {
                int c  = ng * 32 + (j >> 1) * 16 + (j & 1) * 8 + 2 * tig;  // 0..191
                int hh = c >= 96;
                int rr = c - hh * 96;
                int h  = 2 * p + hh;
                float b0, b1, sc = 1.0f;
                if (rr < 32)      { b0 = bqs[h*HD+rr];    b1 = bqs[h*HD+rr+1]; sc = QSCALE; }
                else if (rr < 64) { b0 = bks[h*HD+rr-32]; b1 = bks[h*HD+rr-31]; }
                else              { b0 = bvs[h*HD+rr-64]; b1 = bvs[h*HD+rr-63]; }
                *(__half2*)(QKV + pr0 * QSTR + c) =
                    __floats2half2_rn((acc[i][j][0] + b0) * sc, (acc[i][j][1] + b1) * sc);
                *(__half2*)(QKV + pr1 * QSTR + c) =
                    __floats2half2_rn((acc[i][j][2] + b0) * sc, (acc[i][j][3] + b1) * sc);
            }
        }
        __syncthreads();

        // ===== attention (warps 0..7) || p==1: warps 8..11 stage Wo[0..95] -> X region =====
        if (warp < 8) {
            const int w = warp;
            const uint32_t bbase = sbQKV + (uint32_t)(w * PBR * QSTR) * 2;

            float bias[2][4];
            #pragma unroll
            for (int nt = 0; nt < 2; nt++) {
                int cb = nt * 8 + 2 * tig;
                int r0 = gid, r1 = gid + 8;
                float k0 = (cb < NJ)     ? kmsk[w * NJ + cb]     : 0.0f;
                float k1 = (cb + 1 < NJ) ? kmsk[w * NJ + cb + 1] : 0.0f;
                bias[nt][0] = (r0 < NJ && cb < NJ)     ? adjb[r0 * NJ + cb] + k0     : 0.0f;
                bias[nt][1] = (r0 < NJ && cb + 1 < NJ) ? adjb[r0 * NJ + cb + 1] + k1 : 0.0f;
                bias[nt][2] = (r1 < NJ && cb < NJ)     ? adjb[r1 * NJ + cb] + k0     : 0.0f;
                bias[nt][3] = (r1 < NJ && cb + 1 < NJ) ? adjb[r1 * NJ + cb + 1] + k1 : 0.0f;
            }

            #pragma unroll
            for (int hh = 0; hh < 2; hh++) {
                const uint32_t hb = bbase + hh * 192;

                uint32_t aQ[2][4];
                {
                    uint32_t ad = hb + (uint32_t)((lane & 15) * QSTR) * 2 + ((lane >> 4) * 16);
                    ldsm_x4(aQ[0], ad);
                    ldsm_x4(aQ[1], ad + 32);
                }
                uint32_t bK[2][4];
                {
                    uint32_t ad = hb + (uint32_t)(((lane & 7) + ((lane >> 4) * 8)) * QSTR) * 2
                                + 64 + (((lane >> 3) & 1) * 16);
                    ldsm_x4(bK[0], ad);
                    ldsm_x4(bK[1], ad + 32);
                }

                float sacc[2][4];
                #pragma unroll
                for (int nt = 0; nt < 2; nt++)
                    #pragma unroll
                    for (int r = 0; r < 4; r++) sacc[nt][r] = bias[nt][r];
                #pragma unroll
                for (int ks = 0; ks < 2; ks++) {
                    mma16(sacc[0], aQ[ks], bK[ks]);
                    mma16(sacc[1], aQ[ks], bK[ks] + 2);
                }
                #pragma unroll
                for (int nt = 0; nt < 2; nt++) {
                    int cb = nt * 8 + 2 * tig;
                    if (cb >= NJ)     { sacc[nt][0] = -1e30f; sacc[nt][2] = -1e30f; }
                    if (cb + 1 >= NJ) { sacc[nt][1] = -1e30f; sacc[nt][3] = -1e30f; }
                }

                float m0 = fmaxf(fmaxf(sacc[0][0], sacc[0][1]), fmaxf(sacc[1][0], sacc[1][1]));
                float m1 = fmaxf(fmaxf(sacc[0][2], sacc[0][3]), fmaxf(sacc[1][2], sacc[1][3]));
                m0 = fmaxf(m0, __shfl_xor_sync(0xFFFFFFFFu, m0, 1));
                m0 = fmaxf(m0, __shfl_xor_sync(0xFFFFFFFFu, m0, 2));
                m1 = fmaxf(m1, __shfl_xor_sync(0xFFFFFFFFu, m1, 1));
                m1 = fmaxf(m1, __shfl_xor_sync(0xFFFFFFFFu, m1, 2));

                float e00 = __expf(sacc[0][0] - m0), e01 = __expf(sacc[0][1] - m0);
                float e10 = __expf(sacc[1][0] - m0), e11 = __expf(sacc[1][1] - m0);
                float f00 = __expf(sacc[0][2] - m1), f01 = __expf(sacc[0][3] - m1);
                float f10 = __expf(sacc[1][2] - m1), f11 = __expf(sacc[1][3] - m1);

                float s0 = e00 + e01 + e10 + e11;
                float s1 = f00 + f01 + f10 + f11;
                s0 += __shfl_xor_sync(0xFFFFFFFFu, s0, 1);
                s0 += __shfl_xor_sync(0xFFFFFFFFu, s0, 2);
                s1 += __shfl_xor_sync(0xFFFFFFFFu, s1, 1);
                s1 += __shfl_xor_sync(0xFFFFFFFFu, s1, 2);
                float i0 = 1.0f / s0, i1 = 1.0f / s1;

                uint32_t pa[4];
                pa[0] = h2u(__floats2half2_rn(e00 * i0, e01 * i0));
                pa[1] = h2u(__floats2half2_rn(f00 * i1, f01 * i1));
                pa[2] = h2u(__floats2half2_rn(e10 * i0, e11 * i0));
                pa[3] = h2u(__floats2half2_rn(f10 * i1, f11 * i1));

                uint32_t vb[2][4];
                {
                    uint32_t ad = hb + (uint32_t)((lane & 15) * QSTR) * 2
                                + 128 + ((lane >> 4) * 16);
                    ldsm_x4t(vb[0], ad);
                    ldsm_x4t(vb[1], ad + 32);
                }
                float oacc[4][4];
                #pragma unroll
                for (int j = 0; j < 4; j++)
                    #pragma unroll
                    for (int r = 0; r < 4; r++) oacc[j][r] = 0.0f;
                mma16(oacc[0], pa, vb[0]);
                mma16(oacc[1], pa, vb[0] + 2);
                mma16(oacc[2], pa, vb[1]);
                mma16(oacc[3], pa, vb[1] + 2);

                int hcol = (2 * p + hh) * HD;
                __half* d0 = AOh + (w * NJ + gid) * TSTR + hcol + 2 * tig;
                #pragma unroll
                for (int j = 0; j < 4; j++)
                    *(__half2*)(d0 + j * 8) = __floats2half2_rn(oacc[j][0], oacc[j][1]);
                int r1 = gid + 8;
                if (r1 < NJ) {
                    __half* d1 = AOh + (w * NJ + r1) * TSTR + hcol + 2 * tig;
                    #pragma unroll
                    for (int j = 0; j < 4; j++)
                        *(__half2*)(d1 + j * 8) = __floats2half2_rn(oacc[j][2], oacc[j][3]);
                }
            }
        } else if (p == 1) {
            // warps 8..11: stage Wo rows 0..95 (ALL 16 chunks/row) into the dead X region
            int t2 = tid - 256;                     // 0..127
            #pragma unroll
            for (int j = 0; j < 12; j++) {
                int i = t2 + j * 128;               // < 1536
                int row = i >> 4, ch = (i & 15) * 8;   // 16 uint4 per 128-col row
                cpa16(sbX + (uint32_t)(row * TSTR) * 2 + ch * 2, gWo + row * DM + ch);
            }
            cp_commit();
            cp_wait0();
        }
        __syncthreads();   // QKV reads done (p0) / AO+Wo0-95 ready (p1)

        if (p == 0) {
            // stage W pass 1 (heads 2,3) via cp.async
            #pragma unroll
            for (int j = 0; j < 8; j++) {
                int i = tid + j * THREADS;          // < 3072
                int row = i >> 4, c = (i & 15) * 8;
                int hh  = row >= 96;
                int sub = (row - hh * 96) >> 5;
                cpa16(sbW + (uint32_t)(row * TSTR) * 2 + c * 2,
                      gWqkv + sub * 16384 + ((2 + hh) * HD + (row & 31)) * DM + c);
            }
            cp_commit();
            cp_wait0();
            __syncthreads();
        }
    }

    // ---- stage Wo rows 96..127 (16 chunks/row) into W region ----
    #pragma unroll
    for (int j = 0; j < 2; j++) {
        int i = tid + j * THREADS;
        if (i < 512) {
            int row = i >> 4, ch = (i & 15) * 8;    // row 0..31 -> Wo row 96+row
            cpa16(sbW + (uint32_t)(row * TSTR) * 2 + ch * 2, gWo + (96 + row) * DM + ch);
        }
    }
    cp_commit();
    cp_wait0();
    __syncthreads();

    // ===== final GEMM (12 warps, fm3 x fn4): Y(96x128) = AO @ Wo^T =====
    {
        const int fm = warp >> 2, fn = warp & 3;    // fm 0..2 (32 rows), fn 0..3 (32 cols)
        uint32_t faddr[2], fbaddr[2];
        #pragma unroll
        for (int i = 0; i < 2; i++)
            faddr[i] = sbAO + (uint32_t)((fm * 32 + i * 16 + (lane & 15)) * TSTR) * 2
                            + ((lane >> 4) * 16);
        #pragma unroll
        for (int j = 0; j < 2; j++) {
            int row = fn * 32 + j * 16 + (lane & 7) + ((lane >> 4) * 8);
            uint32_t base = (fn < 3) ? (sbX + (uint32_t)(row * TSTR) * 2)
                                     : (sbW + (uint32_t)((row - 96) * TSTR) * 2);
            fbaddr[j] = base + (((lane >> 3) & 1) * 16);
        }

        float y[2][4][4];
        #pragma unroll
        for (int i = 0; i < 2; i++)
            #pragma unroll
            for (int j = 0; j < 4; j++)
                #pragma unroll
                for (int r = 0; r < 4; r++) y[i][j][r] = 0.0f;

        #pragma unroll
        for (int ks = 0; ks < 8; ks++) {
            uint32_t a[2][4], b[2][4];
            #pragma unroll
            for (int i = 0; i < 2; i++) ldsm_x4(a[i], faddr[i] + ks * 32);
            #pragma unroll
            for (int j = 0; j < 2; j++) ldsm_x4(b[j], fbaddr[j] + ks * 32);
            #pragma unroll
            for (int i = 0; i < 2; i++)
                #pragma unroll
                for (int j = 0; j < 2; j++) {
                    mma16(y[i][2*j],   a[i], b[j]);
                    mma16(y[i][2*j+1], a[i], b[j] + 2);
                }
        }

        #pragma unroll
        for (int i = 0; i < 2; i++) {
            int row = fm * 32 + i * 16 + gid;
            #pragma unroll
            for (int j = 0; j < 4; j++) {
                int col = fn * 32 + j * 8 + 2 * tig;
                float b0 = bos[col], b1 = bos[col + 1];
                size_t base = ((size_t)cta * MR + row) * DM + col;
                *(float2*)(out + base)          = make_float2(y[i][j][0] + b0, y[i][j][1] + b1);
                *(float2*)(out + base + 8 * DM) = make_float2(y[i][j][2] + b0, y[i][j][3] + b1);
            }
        }
    }
}

extern "C" void kernel_launch(void* const* d_in, const int* in_sizes, int n_in,
                              void* d_out, int out_size) {
    const float* x   = (const float*)d_in[0];
    const float* vis = (const float*)d_in[1];
    const float* Wq  = (const float*)d_in[2];
    const float* bq  = (const float*)d_in[3];
    const float* Wk  = (const float*)d_in[4];
    const float* bk  = (const float*)d_in[5];
    const float* Wv  = (const float*)d_in[6];
    const float* bv  = (const float*)d_in[7];
    const float* Wo  = (const float*)d_in[8];
    const float* bo  = (const float*)d_in[9];
    const float* bsc = (const float*)d_in[10];
    const float* adj = (const float*)d_in[11];
    float* out = (float*)d_out;

    const int B = in_sizes[0] / (NJ * DM);      // 16384
    const int grid = B / TB;                    // 2048

    static bool attr_set = false;
    if (!attr_set) {
        cudaFuncSetAttribute(cross_joint_attn_kernel,
                             cudaFuncAttributeMaxDynamicSharedMemorySize, SMEM_BYTES);
        attr_set = true;
    }
    convert_weights<<<16, 256>>>(Wq, Wk, Wv, Wo);
    cross_joint_attn_kernel<<<grid, THREADS, SMEM_BYTES>>>(
        x, vis, bq, bk, bv, bo, bsc, adj, out);
}

// round 16
// speedup vs baseline: 1.0014x; 1.0014x over previous
#include <cuda_runtime.h>
#include <cuda_fp16.h>
#include <cstdint>

#define THREADS 384
#define TB 8
#define NJ 12
#define DM 128
#define NH 4
#define HD 32
#define MR 96              // valid rows per CTA
#define PBR 16             // padded rows per batch

#define TSTR 136           // fp16 tile stride (halves)
#define QSTR 200           // fp16 QKV stride (halves), 2 heads

// smem byte offsets
#define OFF_X    0                          // 96 x 136 h  = 26112 (X, later Wo rows 0..95)
#define OFF_W    26112                      // 192 x 136 h = 52224 (W pass / QKV overlay / Wo rows 96..127)
#define OFF_AO   78336                      // 96 x 136 h  = 26112
#define OFF_BQ   104448
#define OFF_BK   104960
#define OFF_BV   105472
#define OFF_BO   105984
#define OFF_ADJ  106496                     // 144 f32
#define OFF_KM   107072                     // 96 f32
#define SMEM_BYTES 107520

// pre-converted fp16 weights
__device__ __half gWqkv[3 * DM * DM];       // [Wq|Wk|Wv] stacked: sub*16384 + row*128 + col
__device__ __half gWo[DM * DM];

__device__ __forceinline__ uint2 f4_to_h4(float4 v) {
    __half2 a = __floats2half2_rn(v.x, v.y);
    __half2 b = __floats2half2_rn(v.z, v.w);
    uint2 r;
    r.x = *(uint32_t*)&a; r.y = *(uint32_t*)&b;
    return r;
}

__global__ void convert_weights(const float* __restrict__ Wq, const float* __restrict__ Wk,
                                const float* __restrict__ Wv, const float* __restrict__ Wo) {
    int i = blockIdx.x * 256 + threadIdx.x;        // 0..4095
    *(uint2*)(gWqkv + 0*16384 + i*4) = f4_to_h4(((const float4*)Wq)[i]);
    *(uint2*)(gWqkv + 1*16384 + i*4) = f4_to_h4(((const float4*)Wk)[i]);
    *(uint2*)(gWqkv + 2*16384 + i*4) = f4_to_h4(((const float4*)Wv)[i]);
    *(uint2*)(gWo + i*4)             = f4_to_h4(((const float4*)Wo)[i]);
}

__device__ __forceinline__ void ldsm_x4(uint32_t* r, uint32_t addr) {
    asm volatile("ldmatrix.sync.aligned.m8n8.x4.shared.b16 {%0,%1,%2,%3}, [%4];"
        : "=r"(r[0]), "=r"(r[1]), "=r"(r[2]), "=r"(r[3]) : "r"(addr));
}
__device__ __forceinline__ void ldsm_x4t(uint32_t* r, uint32_t addr) {
    asm volatile("ldmatrix.sync.aligned.m8n8.x4.trans.shared.b16 {%0,%1,%2,%3}, [%4];"
        : "=r"(r[0]), "=r"(r[1]), "=r"(r[2]), "=r"(r[3]) : "r"(addr));
}
__device__ __forceinline__ void stsm_x4(uint32_t addr, uint32_t r0, uint32_t r1,
                                        uint32_t r2, uint32_t r3) {
    asm volatile("stmatrix.sync.aligned.m8n8.x4.shared.b16 [%0], {%1,%2,%3,%4};"
        :: "r"(addr), "r"(r0), "r"(r1), "r"(r2), "r"(r3) : "memory");
}
__device__ __forceinline__ void mma16(float* d, const uint32_t* a, const uint32_t* b) {
    asm volatile(
        "mma.sync.aligned.m16n8k16.row.col.f32.f16.f16.f32 "
        "{%0,%1,%2,%3}, {%4,%5,%6,%7}, {%8,%9}, {%0,%1,%2,%3};"
        : "+f"(d[0]), "+f"(d[1]), "+f"(d[2]), "+f"(d[3])
        : "r"(a[0]), "r"(a[1]), "r"(a[2]), "r"(a[3]), "r"(b[0]), "r"(b[1]));
}
__device__ __forceinline__ uint32_t h2u(__half2 h) { return *(uint32_t*)&h; }

__device__ __forceinline__ void cpa16(uint32_t saddr, const void* gptr) {
    asm volatile("cp.async.cg.shared.global [%0], [%1], 16;"
        :: "r"(saddr), "l"(__cvta_generic_to_global(gptr)) : "memory");
}
__device__ __forceinline__ void cp_commit() {
    asm volatile("cp.async.commit_group;" ::: "memory");
}
__device__ __forceinline__ void cp_wait0() {
    asm volatile("cp.async.wait_group 0;" ::: "memory");
}

__global__ void __launch_bounds__(THREADS, 2)
cross_joint_attn_kernel(
    const float* __restrict__ x, const float* __restrict__ vis,
    const float* __restrict__ bq, const float* __restrict__ bk,
    const float* __restrict__ bv, const float* __restrict__ bo,
    const float* __restrict__ bias_scale, const float* __restrict__ adj,
    float* __restrict__ out)
{
    extern __shared__ __align__(16) char smc[];
    __half* Xh  = (__half*)(smc + OFF_X);
    __half* QKV = (__half*)(smc + OFF_W);     // overlay on W
    __half* AOh = (__half*)(smc + OFF_AO);
    float* bqs  = (float*)(smc + OFF_BQ);
    float* bks  = (float*)(smc + OFF_BK);
    float* bvs  = (float*)(smc + OFF_BV);
    float* bos  = (float*)(smc + OFF_BO);
    float* adjb = (float*)(smc + OFF_ADJ);
    float* kmsk = (float*)(smc + OFF_KM);

    const int tid  = threadIdx.x;
    const int lane = tid & 31;
    const int warp = tid >> 5;
    const int cta  = blockIdx.x;
    const int gid  = lane >> 2;
    const int tig  = lane & 3;

    const uint32_t sb    = (uint32_t)__cvta_generic_to_shared(smc);
    const uint32_t sbX   = sb + OFF_X;
    const uint32_t sbW   = sb + OFF_W;
    const uint32_t sbQKV = sb + OFF_W;
    const uint32_t sbAO  = sb + OFF_AO;

    // ---- stage W pass 0 (heads 0,1) via cp.async, then X (fp32->fp16) ----
    #pragma unroll
    for (int j = 0; j < 8; j++) {
        int i = tid + j * THREADS;                 // < 3072 uint4
        int row = i >> 4, c = (i & 15) * 8;
        int hh  = row >= 96;
        int sub = (row - hh * 96) >> 5;            // 0=Wq 1=Wk 2=Wv
        cpa16(sbW + (uint32_t)(row * TSTR) * 2 + c * 2,
              gWqkv + sub * 16384 + (hh * HD + (row & 31)) * DM + c);
    }
    cp_commit();
    {
        const float4* xg = (const float4*)(x + (size_t)cta * MR * DM);
        #pragma unroll
        for (int j = 0; j < 8; j++) {
            int i = tid + j * THREADS;             // < 3072
            int row = i >> 5, kk = (i & 31) * 4;
            *(uint2*)(Xh + row * TSTR + kk) = f4_to_h4(xg[i]);
        }
    }
    if (tid < DM) {
        bqs[tid] = bq[tid]; bks[tid] = bk[tid];
        bvs[tid] = bv[tid]; bos[tid] = bo[tid];
    }
    if (tid < NJ * NJ) adjb[tid] = adj[tid] * bias_scale[0];
    if (tid < MR)      kmsk[tid] = -10.0f * (1.0f - vis[(size_t)cta * MR + tid]);
    cp_wait0();
    __syncthreads();

    // GEMM1 tiling: 12 warps, mg2 (48 rows) x ng6 (32 cols)
    const int mg = warp / 6, ng = warp - mg * 6;
    uint32_t aaddr[3], baddr[2];
    #pragma unroll
    for (int i = 0; i < 3; i++)
        aaddr[i] = sbX + (uint32_t)((mg * 48 + i * 16 + (lane & 15)) * TSTR) * 2
                       + ((lane >> 4) * 16);
    #pragma unroll
    for (int j = 0; j < 2; j++)
        baddr[j] = sbW + (uint32_t)((ng * 32 + j * 16 + (lane & 7) + ((lane >> 4) * 8)) * TSTR) * 2
                       + (((lane >> 3) & 1) * 16);

    const float QSCALE = 0.17677669529663687f;

    // stmatrix per-lane row address precompute pieces
    const int sm_m  = lane >> 3;                   // matrix index 0..3
    const int sm_rl = lane & 7;                    // row within matrix

    for (int p = 0; p < 2; ++p) {
        // ===== GEMM1: QKV(96x192) = X @ [Wq|Wk|Wv]_{2p,2p+1}^T =====
        float acc[3][4][4];
        #pragma unroll
        for (int i = 0; i < 3; i++)
            #pragma unroll
            for (int j = 0; j < 4; j++)
                #pragma unroll
                for (int r = 0; r < 4; r++) acc[i][j][r] = 0.0f;

        #pragma unroll
        for (int ks = 0; ks < 8; ks++) {
            uint32_t a[3][4], b[2][4];
            #pragma unroll
            for (int i = 0; i < 3; i++) ldsm_x4(a[i], aaddr[i] + ks * 32);
            #pragma unroll
            for (int j = 0; j < 2; j++) ldsm_x4(b[j], baddr[j] + ks * 32);
            #pragma unroll
            for (int i = 0; i < 3; i++)
                #pragma unroll
                for (int j = 0; j < 2; j++) {
                    mma16(acc[i][2*j],   a[i], b[j]);
                    mma16(acc[i][2*j+1], a[i], b[j] + 2);
                }
        }
        __syncthreads();   // all W (and X, for p=1) reads done before overlay writes

        // bias (+Q prescale) + stmatrix scatter to batch-padded fp16 QKV
        // acc[i][j] covers rows mg*48+i*16 +{gid, gid+8}, cols ng*32 + j*8 + 2tig
        #pragma unroll
        for (int i = 0; i < 3; i++) {
            // per-lane stmatrix row address for this i
            int grow = mg * 48 + i * 16 + ((sm_m & 1) << 3) + sm_rl;
            int pr   = (grow / NJ) * PBR + (grow % NJ);
            #pragma unroll
            for (int g = 0; g < 2; g++) {
                int j0 = 2 * g, j1 = 2 * g + 1;
                // bias for tile j0 (this lane's element cols)
                int c0 = ng * 32 + j0 * 8 + 2 * tig;
                int c1 = ng * 32 + j1 * 8 + 2 * tig;
                float b00, b01, sc0 = 1.0f, b10, b11, sc1 = 1.0f;
                {
                    int hh = c0 >= 96; int rr = c0 - hh * 96; int h = 2 * p + hh;
                    if (rr < 32)      { b00 = bqs[h*HD+rr];    b01 = bqs[h*HD+rr+1]; sc0 = QSCALE; }
                    else if (rr < 64) { b00 = bks[h*HD+rr-32]; b01 = bks[h*HD+rr-31]; }
                    else              { b00 = bvs[h*HD+rr-64]; b01 = bvs[h*HD+rr-63]; }
                }
                {
                    int hh = c1 >= 96; int rr = c1 - hh * 96; int h = 2 * p + hh;
                    if (rr < 32)      { b10 = bqs[h*HD+rr];    b11 = bqs[h*HD+rr+1]; sc1 = QSCALE; }
                    else if (rr < 64) { b10 = bks[h*HD+rr-32]; b11 = bks[h*HD+rr-31]; }
                    else              { b10 = bvs[h*HD+rr-64]; b11 = bvs[h*HD+rr-63]; }
                }
                uint32_t r0 = h2u(__floats2half2_rn((acc[i][j0][0] + b00) * sc0,
                                                    (acc[i][j0][1] + b01) * sc0));
                uint32_t r1 = h2u(__floats2half2_rn((acc[i][j0][2] + b00) * sc0,
                                                    (acc[i][j0][3] + b01) * sc0));
                uint32_t r2 = h2u(__floats2half2_rn((acc[i][j1][0] + b10) * sc1,
                                                    (acc[i][j1][1] + b11) * sc1));
                uint32_t r3 = h2u(__floats2half2_rn((acc[i][j1][2] + b10) * sc1,
                                                    (acc[i][j1][3] + b11) * sc1));
                // lane address: matrix m -> col tile j0 + (m>>1), rows low/high by m&1
                int colm = ng * 32 + (j0 + (sm_m >> 1)) * 8;
                uint32_t addr = sbQKV + (uint32_t)pr * (QSTR * 2) + colm * 2;
                stsm_x4(addr, r0, r1, r2, r3);
            }
        }
        __syncthreads();

        // ===== attention (warps 0..7) || p==1: warps 8..11 stage Wo[0..95] -> X region =====
        if (warp < 8) {
            const int w = warp;
            const uint32_t bbase = sbQKV + (uint32_t)(w * PBR * QSTR) * 2;

            float bias[2][4];
            #pragma unroll
            for (int nt = 0; nt < 2; nt++) {
                int cb = nt * 8 + 2 * tig;
                int r0 = gid, r1 = gid + 8;
                float k0 = (cb < NJ)     ? kmsk[w * NJ + cb]     : 0.0f;
                float k1 = (cb + 1 < NJ) ? kmsk[w * NJ + cb + 1] : 0.0f;
                bias[nt][0] = (r0 < NJ && cb < NJ)     ? adjb[r0 * NJ + cb] + k0     : 0.0f;
                bias[nt][1] = (r0 < NJ && cb + 1 < NJ) ? adjb[r0 * NJ + cb + 1] + k1 : 0.0f;
                bias[nt][2] = (r1 < NJ && cb < NJ)     ? adjb[r1 * NJ + cb] + k0     : 0.0f;
                bias[nt][3] = (r1 < NJ && cb + 1 < NJ) ? adjb[r1 * NJ + cb + 1] + k1 : 0.0f;
            }

            #pragma unroll
            for (int hh = 0; hh < 2; hh++) {
                const uint32_t hb = bbase + hh * 192;

                uint32_t aQ[2][4];
                {
                    uint32_t ad = hb + (uint32_t)((lane & 15) * QSTR) * 2 + ((lane >> 4) * 16);
                    ldsm_x4(aQ[0], ad);
                    ldsm_x4(aQ[1], ad + 32);
                }
                uint32_t bK[2][4];
                {
                    uint32_t ad = hb + (uint32_t)(((lane & 7) + ((lane >> 4) * 8)) * QSTR) * 2
                                + 64 + (((lane >> 3) & 1) * 16);
                    ldsm_x4(bK[0], ad);
                    ldsm_x4(bK[1], ad + 32);
                }

                float sacc[2][4];
                #pragma unroll
                for (int nt = 0; nt < 2; nt++)
                    #pragma unroll
                    for (int r = 0; r < 4; r++) sacc[nt][r] = bias[nt][r];
                #pragma unroll
                for (int ks = 0; ks < 2; ks++) {
                    mma16(sacc[0], aQ[ks], bK[ks]);
                    mma16(sacc[1], aQ[ks], bK[ks] + 2);
                }
                #pragma unroll
                for (int nt = 0; nt < 2; nt++) {
                    int cb = nt * 8 + 2 * tig;
                    if (cb >= NJ)     { sacc[nt][0] = -1e30f; sacc[nt][2] = -1e30f; }
                    if (cb + 1 >= NJ) { sacc[nt][1] = -1e30f; sacc[nt][3] = -1e30f; }
                }

                float m0 = fmaxf(fmaxf(sacc[0][0], sacc[0][1]), fmaxf(sacc[1][0], sacc[1][1]));
                float m1 = fmaxf(fmaxf(sacc[0][2], sacc[0][3]), fmaxf(sacc[1][2], sacc[1][3]));
                m0 = fmaxf(m0, __shfl_xor_sync(0xFFFFFFFFu, m0, 1));
                m0 = fmaxf(m0, __shfl_xor_sync(0xFFFFFFFFu, m0, 2));
                m1 = fmaxf(m1, __shfl_xor_sync(0xFFFFFFFFu, m1, 1));
                m1 = fmaxf(m1, __shfl_xor_sync(0xFFFFFFFFu, m1, 2));

                float e00 = __expf(sacc[0][0] - m0), e01 = __expf(sacc[0][1] - m0);
                float e10 = __expf(sacc[1][0] - m0), e11 = __expf(sacc[1][1] - m0);
                float f00 = __expf(sacc[0][2] - m1), f01 = __expf(sacc[0][3] - m1);
                float f10 = __expf(sacc[1][2] - m1), f11 = __expf(sacc[1][3] - m1);

                float s0 = e00 + e01 + e10 + e11;
                float s1 = f00 + f01 + f10 + f11;
                s0 += __shfl_xor_sync(0xFFFFFFFFu, s0, 1);
                s0 += __shfl_xor_sync(0xFFFFFFFFu, s0, 2);
                s1 += __shfl_xor_sync(0xFFFFFFFFu, s1, 1);
                s1 += __shfl_xor_sync(0xFFFFFFFFu, s1, 2);
                float i0 = 1.0f / s0, i1 = 1.0f / s1;

                uint32_t pa[4];
                pa[0] = h2u(__floats2half2_rn(e00 * i0, e01 * i0));
                pa[1] = h2u(__floats2half2_rn(f00 * i1, f01 * i1));
                pa[2] = h2u(__floats2half2_rn(e10 * i0, e11 * i0));
                pa[3] = h2u(__floats2half2_rn(f10 * i1, f11 * i1));

                uint32_t vb[2][4];
                {
                    uint32_t ad = hb + (uint32_t)((lane & 15) * QSTR) * 2
                                + 128 + ((lane >> 4) * 16);
                    ldsm_x4t(vb[0], ad);
                    ldsm_x4t(vb[1], ad + 32);
                }
                float oacc[4][4];
                #pragma unroll
                for (int j = 0; j < 4; j++)
                    #pragma unroll
                    for (int r = 0; r < 4; r++) oacc[j][r] = 0.0f;
                mma16(oacc[0], pa, vb[0]);
                mma16(oacc[1], pa, vb[0] + 2);
                mma16(oacc[2], pa, vb[1]);
                mma16(oacc[3], pa, vb[1] + 2);

                int hcol = (2 * p + hh) * HD;
                __half* d0 = AOh + (w * NJ + gid) * TSTR + hcol + 2 * tig;
                #pragma unroll
                for (int j = 0; j < 4; j++)
                    *(__half2*)(d0 + j * 8) = __floats2half2_rn(oacc[j][0], oacc[j][1]);
                int r1 = gid + 8;
                if (r1 < NJ) {
                    __half* d1 = AOh + (w * NJ + r1) * TSTR + hcol + 2 * tig;
                    #pragma unroll
                    for (int j = 0; j < 4; j++)
                        *(__half2*)(d1 + j * 8) = __floats2half2_rn(oacc[j][2], oacc[j][3]);
                }
            }
        } else if (p == 1) {
            // warps 8..11: stage Wo rows 0..95 (16 chunks/row) into the dead X region
            int t2 = tid - 256;                     // 0..127
            #pragma unroll
            for (int j = 0; j < 12; j++) {
                int i = t2 + j * 128;               // < 1536
                int row = i >> 4, ch = (i & 15) * 8;
                cpa16(sbX + (uint32_t)(row * TSTR) * 2 + ch * 2, gWo + row * DM + ch);
            }
            cp_commit();
            cp_wait0();
        }
        __syncthreads();   // QKV reads done (p0) / AO+Wo0-95 ready (p1)

        if (p == 0) {
            // stage W pass 1 (heads 2,3) via cp.async
            #pragma unroll
            for (int j = 0; j < 8; j++) {
                int i = tid + j * THREADS;          // < 3072
                int row = i >> 4, c = (i & 15) * 8;
                int hh  = row >= 96;
                int sub = (row - hh * 96) >> 5;
                cpa16(sbW + (uint32_t)(row * TSTR) * 2 + c * 2,
                      gWqkv + sub * 16384 + ((2 + hh) * HD + (row & 31)) * DM + c);
            }
            cp_commit();
            cp_wait0();
            __syncthreads();
        }
    }

    // ---- stage Wo rows 96..127 (16 chunks/row) into W region ----
    #pragma unroll
    for (int j = 0; j < 2; j++) {
        int i = tid + j * THREADS;
        if (i < 512) {
            int row = i >> 4, ch = (i & 15) * 8;    // row 0..31 -> Wo row 96+row
            cpa16(sbW + (uint32_t)(row * TSTR) * 2 + ch * 2, gWo + (96 + row) * DM + ch);
        }
    }
    cp_commit();
    cp_wait0();
    __syncthreads();

    // ===== final GEMM (12 warps, fm3 x fn4): Y(96x128) = AO @ Wo^T =====
    {
        const int fm = warp >> 2, fn = warp & 3;    // fm 0..2 (32 rows), fn 0..3 (32 cols)
        uint32_t faddr[2], fbaddr[2];
        #pragma unroll
        for (int i = 0; i < 2; i++)
            faddr[i] = sbAO + (uint32_t)((fm * 32 + i * 16 + (lane & 15)) * TSTR) * 2
                            + ((lane >> 4) * 16);
        #pragma unroll
        for (int j = 0; j < 2; j++) {
            int row = fn * 32 + j * 16 + (lane & 7) + ((lane >> 4) * 8);
            uint32_t base = (fn < 3) ? (sbX + (uint32_t)(row * TSTR) * 2)
                                     : (sbW + (uint32_t)((row - 96) * TSTR) * 2);
            fbaddr[j] = base + (((lane >> 3) & 1) * 16);
        }

        float y[2][4][4];
        #pragma unroll
        for (int i = 0; i < 2; i++)
            #pragma unroll
            for (int j = 0; j < 4; j++)
                #pragma unroll
                for (int r = 0; r < 4; r++) y[i][j][r] = 0.0f;

        #pragma unroll
        for (int ks = 0; ks < 8; ks++) {
            uint32_t a[2][4], b[2][4];
            #pragma unroll
            for (int i = 0; i < 2; i++) ldsm_x4(a[i], faddr[i] + ks * 32);
            #pragma unroll
            for (int j = 0; j < 2; j++) ldsm_x4(b[j], fbaddr[j] + ks * 32);
            #pragma unroll
            for (int i = 0; i < 2; i++)
                #pragma unroll
                for (int j = 0; j < 2; j++) {
                    mma16(y[i][2*j],   a[i], b[j]);
                    mma16(y[i][2*j+1], a[i], b[j] + 2);
                }
        }

        #pragma unroll
        for (int i = 0; i < 2; i++) {
            int row = fm * 32 + i * 16 + gid;
            #pragma unroll
            for (int j = 0; j < 4; j++) {
                int col = fn * 32 + j * 8 + 2 * tig;
                float b0 = bos[col], b1 = bos[col + 1];
                size_t base = ((size_t)cta * MR + row) * DM + col;
                *(float2*)(out + base)          = make_float2(y[i][j][0] + b0, y[i][j][1] + b1);
                *(float2*)(out + base + 8 * DM) = make_float2(y[i][j][2] + b0, y[i][j][3] + b1);
            }
        }
    }
}

extern "C" void kernel_launch(void* const* d_in, const int* in_sizes, int n_in,
                              void* d_out, int out_size) {
    const float* x   = (const float*)d_in[0];
    const float* vis = (const float*)d_in[1];
    const float* Wq  = (const float*)d_in[2];
    const float* bq  = (const float*)d_in[3];
    const float* Wk  = (const float*)d_in[4];
    const float* bk  = (const float*)d_in[5];
    const float* Wv  = (const float*)d_in[6];
    const float* bv  = (const float*)d_in[7];
    const float* Wo  = (const float*)d_in[8];
    const float* bo  = (const float*)d_in[9];
    const float* bsc = (const float*)d_in[10];
    const float* adj = (const float*)d_in[11];
    float* out = (float*)d_out;

    const int B = in_sizes[0] / (NJ * DM);      // 16384
    const int grid = B / TB;                    // 2048

    static bool attr_set = false;
    if (!attr_set) {
        cudaFuncSetAttribute(cross_joint_attn_kernel,
                             cudaFuncAttributeMaxDynamicSharedMemorySize, SMEM_BYTES);
        attr_set = true;
    }
    convert_weights<<<16, 256>>>(Wq, Wk, Wv, Wo);
    cross_joint_attn_kernel<<<grid, THREADS, SMEM_BYTES>>>(
        x, vis, bq, bk, bv, bo, bsc, adj, out);
}

// round 17
// speedup vs baseline: 1.0034x; 1.0019x over previous
#include <cuda_runtime.h>
#include <cuda_fp16.h>
#include <cstdint>

#define THREADS 384
#define TB 8
#define NJ 12
#define DM 128
#define NH 4
#define HD 32
#define MR 96              // valid rows per CTA
#define PBR 16             // padded rows per batch

#define TSTR 136           // fp16 tile stride (halves)
#define QSTR 200           // fp16 QKV stride (halves), 2 heads

// smem byte offsets
#define OFF_X    0                          // 96 x 136 h  = 26112 (X, later Wo rows 0..95)
#define OFF_W    26112                      // 192 x 136 h = 52224 (W pass / QKV overlay / Wo rows 96..127)
#define OFF_AO   78336                      // 96 x 136 h  = 26112
#define OFF_BQ   104448
#define OFF_BK   104960
#define OFF_BV   105472
#define OFF_BO   105984
#define OFF_ADJ  106496                     // 144 f32
#define OFF_KM   107072                     // 96 f32
#define SMEM_BYTES 107520

// pre-converted fp16 weights
__device__ __half gWqkv[3 * DM * DM];       // [Wq|Wk|Wv] stacked: sub*16384 + row*128 + col
__device__ __half gWo[DM * DM];

__device__ __forceinline__ uint2 f4_to_h4(float4 v) {
    __half2 a = __floats2half2_rn(v.x, v.y);
    __half2 b = __floats2half2_rn(v.z, v.w);
    uint2 r;
    r.x = *(uint32_t*)&a; r.y = *(uint32_t*)&b;
    return r;
}

__global__ void convert_weights(const float* __restrict__ Wq, const float* __restrict__ Wk,
                                const float* __restrict__ Wv, const float* __restrict__ Wo) {
    int i = blockIdx.x * 256 + threadIdx.x;        // 0..4095
    *(uint2*)(gWqkv + 0*16384 + i*4) = f4_to_h4(((const float4*)Wq)[i]);
    *(uint2*)(gWqkv + 1*16384 + i*4) = f4_to_h4(((const float4*)Wk)[i]);
    *(uint2*)(gWqkv + 2*16384 + i*4) = f4_to_h4(((const float4*)Wv)[i]);
    *(uint2*)(gWo + i*4)             = f4_to_h4(((const float4*)Wo)[i]);
}

__device__ __forceinline__ void ldsm_x4(uint32_t* r, uint32_t addr) {
    asm volatile("ldmatrix.sync.aligned.m8n8.x4.shared.b16 {%0,%1,%2,%3}, [%4];"
        : "=r"(r[0]), "=r"(r[1]), "=r"(r[2]), "=r"(r[3]) : "r"(addr));
}
__device__ __forceinline__ void ldsm_x4t(uint32_t* r, uint32_t addr) {
    asm volatile("ldmatrix.sync.aligned.m8n8.x4.trans.shared.b16 {%0,%1,%2,%3}, [%4];"
        : "=r"(r[0]), "=r"(r[1]), "=r"(r[2]), "=r"(r[3]) : "r"(addr));
}
__device__ __forceinline__ void stsm_x4(uint32_t addr, uint32_t r0, uint32_t r1,
                                        uint32_t r2, uint32_t r3) {
    asm volatile("stmatrix.sync.aligned.m8n8.x4.shared.b16 [%0], {%1,%2,%3,%4};"
        :: "r"(addr), "r"(r0), "r"(r1), "r"(r2), "r"(r3) : "memory");
}
__device__ __forceinline__ void mma16(float* d, const uint32_t* a, const uint32_t* b) {
    asm volatile(
        "mma.sync.aligned.m16n8k16.row.col.f32.f16.f16.f32 "
        "{%0,%1,%2,%3}, {%4,%5,%6,%7}, {%8,%9}, {%0,%1,%2,%3};"
        : "+f"(d[0]), "+f"(d[1]), "+f"(d[2]), "+f"(d[3])
        : "r"(a[0]), "r"(a[1]), "r"(a[2]), "r"(a[3]), "r"(b[0]), "r"(b[1]));
}
__device__ __forceinline__ uint32_t h2u(__half2 h) { return *(uint32_t*)&h; }

__device__ __forceinline__ void cpa16(uint32_t saddr, const void* gptr) {
    asm volatile("cp.async.cg.shared.global [%0], [%1], 16;"
        :: "r"(saddr), "l"(__cvta_generic_to_global(gptr)) : "memory");
}
__device__ __forceinline__ void cp_commit() {
    asm volatile("cp.async.commit_group;" ::: "memory");
}
__device__ __forceinline__ void cp_wait0() {
    asm volatile("cp.async.wait_group 0;" ::: "memory");
}

__global__ void __launch_bounds__(THREADS, 2)
cross_joint_attn_kernel(
    const float* __restrict__ x, const float* __restrict__ vis,
    const float* __restrict__ bq, const float* __restrict__ bk,
    const float* __restrict__ bv, const float* __restrict__ bo,
    const float* __restrict__ bias_scale, const float* __restrict__ adj,
    float* __restrict__ out)
{
    extern __shared__ __align__(16) char smc[];
    __half* Xh  = (__half*)(smc + OFF_X);
    __half* QKV = (__half*)(smc + OFF_W);     // overlay on W
    __half* AOh = (__half*)(smc + OFF_AO);
    float* bqs  = (float*)(smc + OFF_BQ);
    float* bks  = (float*)(smc + OFF_BK);
    float* bvs  = (float*)(smc + OFF_BV);
    float* bos  = (float*)(smc + OFF_BO);
    float* adjb = (float*)(smc + OFF_ADJ);
    float* kmsk = (float*)(smc + OFF_KM);

    const int tid  = threadIdx.x;
    const int lane = tid & 31;
    const int warp = tid >> 5;
    const int cta  = blockIdx.x;
    const int gid  = lane >> 2;
    const int tig  = lane & 3;

    const uint32_t sb    = (uint32_t)__cvta_generic_to_shared(smc);
    const uint32_t sbX   = sb + OFF_X;
    const uint32_t sbW   = sb + OFF_W;
    const uint32_t sbQKV = sb + OFF_W;
    const uint32_t sbAO  = sb + OFF_AO;

    // ---- stage W pass 0 (heads 0,1) via cp.async, then X (fp32->fp16) ----
    #pragma unroll
    for (int j = 0; j < 8; j++) {
        int i = tid + j * THREADS;                 // < 3072 uint4
        int row = i >> 4, c = (i & 15) * 8;
        int hh  = row >= 96;
        int sub = (row - hh * 96) >> 5;            // 0=Wq 1=Wk 2=Wv
        cpa16(sbW + (uint32_t)(row * TSTR) * 2 + c * 2,
              gWqkv + sub * 16384 + (hh * HD + (row & 31)) * DM + c);
    }
    cp_commit();
    {
        const float4* xg = (const float4*)(x + (size_t)cta * MR * DM);
        #pragma unroll
        for (int j = 0; j < 8; j++) {
            int i = tid + j * THREADS;             // < 3072
            int row = i >> 5, kk = (i & 31) * 4;
            *(uint2*)(Xh + row * TSTR + kk) = f4_to_h4(xg[i]);
        }
    }
    if (tid < DM) {
        bqs[tid] = bq[tid]; bks[tid] = bk[tid];
        bvs[tid] = bv[tid]; bos[tid] = bo[tid];
    }
    if (tid < NJ * NJ) adjb[tid] = adj[tid] * bias_scale[0];
    if (tid < MR)      kmsk[tid] = -10.0f * (1.0f - vis[(size_t)cta * MR + tid]);
    cp_wait0();
    __syncthreads();

    // GEMM1 tiling: 12 warps, mg2 (48 rows) x ng6 (32 cols)
    const int mg = warp / 6, ng = warp - mg * 6;
    uint32_t aaddr[3], baddr[2];
    #pragma unroll
    for (int i = 0; i < 3; i++)
        aaddr[i] = sbX + (uint32_t)((mg * 48 + i * 16 + (lane & 15)) * TSTR) * 2
                       + ((lane >> 4) * 16);
    #pragma unroll
    for (int j = 0; j < 2; j++)
        baddr[j] = sbW + (uint32_t)((ng * 32 + j * 16 + (lane & 7) + ((lane >> 4) * 8)) * TSTR) * 2
                       + (((lane >> 3) & 1) * 16);

    const float QSCALE = 0.17677669529663687f;

    // stmatrix per-lane row address precompute pieces
    const int sm_m  = lane >> 3;                   // matrix index 0..3
    const int sm_rl = lane & 7;                    // row within matrix

    for (int p = 0; p < 2; ++p) {
        // ===== GEMM1: QKV(96x192) = X @ [Wq|Wk|Wv]_{2p,2p+1}^T =====
        float acc[3][4][4];
        #pragma unroll
        for (int i = 0; i < 3; i++)
            #pragma unroll
            for (int j = 0; j < 4; j++)
                #pragma unroll
                for (int r = 0; r < 4; r++) acc[i][j][r] = 0.0f;

        #pragma unroll
        for (int ks = 0; ks < 8; ks++) {
            uint32_t a[3][4], b[2][4];
            #pragma unroll
            for (int i = 0; i < 3; i++) ldsm_x4(a[i], aaddr[i] + ks * 32);
            #pragma unroll
            for (int j = 0; j < 2; j++) ldsm_x4(b[j], baddr[j] + ks * 32);
            #pragma unroll
            for (int i = 0; i < 3; i++)
                #pragma unroll
                for (int j = 0; j < 2; j++) {
                    mma16(acc[i][2*j],   a[i], b[j]);
                    mma16(acc[i][2*j+1], a[i], b[j] + 2);
                }
        }
        __syncthreads();   // all W (and X, for p=1) reads done before overlay writes

        // bias (+Q prescale) + stmatrix scatter to batch-padded fp16 QKV
        // acc[i][j] covers rows mg*48+i*16 +{gid, gid+8}, cols ng*32 + j*8 + 2tig
        #pragma unroll
        for (int i = 0; i < 3; i++) {
            // per-lane stmatrix row address for this i
            int grow = mg * 48 + i * 16 + ((sm_m & 1) << 3) + sm_rl;
            int pr   = (grow / NJ) * PBR + (grow % NJ);
            #pragma unroll
            for (int g = 0; g < 2; g++) {
                int j0 = 2 * g, j1 = 2 * g + 1;
                // bias for tile j0 (this lane's element cols)
                int c0 = ng * 32 + j0 * 8 + 2 * tig;
                int c1 = ng * 32 + j1 * 8 + 2 * tig;
                float b00, b01, sc0 = 1.0f, b10, b11, sc1 = 1.0f;
                {
                    int hh = c0 >= 96; int rr = c0 - hh * 96; int h = 2 * p + hh;
                    if (rr < 32)      { b00 = bqs[h*HD+rr];    b01 = bqs[h*HD+rr+1]; sc0 = QSCALE; }
                    else if (rr < 64) { b00 = bks[h*HD+rr-32]; b01 = bks[h*HD+rr-31]; }
                    else              { b00 = bvs[h*HD+rr-64]; b01 = bvs[h*HD+rr-63]; }
                }
                {
                    int hh = c1 >= 96; int rr = c1 - hh * 96; int h = 2 * p + hh;
                    if (rr < 32)      { b10 = bqs[h*HD+rr];    b11 = bqs[h*HD+rr+1]; sc1 = QSCALE; }
                    else if (rr < 64) { b10 = bks[h*HD+rr-32]; b11 = bks[h*HD+rr-31]; }
                    else              { b10 = bvs[h*HD+rr-64]; b11 = bvs[h*HD+rr-63]; }
                }
                uint32_t r0 = h2u(__floats2half2_rn((acc[i][j0][0] + b00) * sc0,
                                                    (acc[i][j0][1] + b01) * sc0));
                uint32_t r1 = h2u(__floats2half2_rn((acc[i][j0][2] + b00) * sc0,
                                                    (acc[i][j0][3] + b01) * sc0));
                uint32_t r2 = h2u(__floats2half2_rn((acc[i][j1][0] + b10) * sc1,
                                                    (acc[i][j1][1] + b11) * sc1));
                uint32_t r3 = h2u(__floats2half2_rn((acc[i][j1][2] + b10) * sc1,
                                                    (acc[i][j1][3] + b11) * sc1));
                // lane address: matrix m -> col tile j0 + (m>>1), rows low/high by m&1
                int colm = ng * 32 + (j0 + (sm_m >> 1)) * 8;
                uint32_t addr = sbQKV + (uint32_t)pr * (QSTR * 2) + colm * 2;
                stsm_x4(addr, r0, r1, r2, r3);
            }
        }
        __syncthreads();

        // ===== attention (warps 0..7) || p==1: warps 8..11 stage Wo[0..95] -> X region =====
        if (warp < 8) {
            const int w = warp;
            const uint32_t bbase = sbQKV + (uint32_t)(w * PBR * QSTR) * 2;

            float bias[2][4];
            #pragma unroll
            for (int nt = 0; nt < 2; nt++) {
                int cb = nt * 8 + 2 * tig;
                int r0 = gid, r1 = gid + 8;
                float k0 = (cb < NJ)     ? kmsk[w * NJ + cb]     : 0.0f;
                float k1 = (cb + 1 < NJ) ? kmsk[w * NJ + cb + 1] : 0.0f;
                bias[nt][0] = (r0 < NJ && cb < NJ)     ? adjb[r0 * NJ + cb] + k0     : 0.0f;
                bias[nt][1] = (r0 < NJ && cb + 1 < NJ) ? adjb[r0 * NJ + cb + 1] + k1 : 0.0f;
                bias[nt][2] = (r1 < NJ && cb < NJ)     ? adjb[r1 * NJ + cb] + k0     : 0.0f;
                bias[nt][3] = (r1 < NJ && cb + 1 < NJ) ? adjb[r1 * NJ + cb + 1] + k1 : 0.0f;
            }

            #pragma unroll
            for (int hh = 0; hh < 2; hh++) {
                const uint32_t hb = bbase + hh * 192;

                uint32_t aQ[2][4];
                {
                    uint32_t ad = hb + (uint32_t)((lane & 15) * QSTR) * 2 + ((lane >> 4) * 16);
                    ldsm_x4(aQ[0], ad);
                    ldsm_x4(aQ[1], ad + 32);
                }
                uint32_t bK[2][4];
                {
                    uint32_t ad = hb + (uint32_t)(((lane & 7) + ((lane >> 4) * 8)) * QSTR) * 2
                                + 64 + (((lane >> 3) & 1) * 16);
                    ldsm_x4(bK[0], ad);
                    ldsm_x4(bK[1], ad + 32);
                }

                float sacc[2][4];
                #pragma unroll
                for (int nt = 0; nt < 2; nt++)
                    #pragma unroll
                    for (int r = 0; r < 4; r++) sacc[nt][r] = bias[nt][r];
                #pragma unroll
                for (int ks = 0; ks < 2; ks++) {
                    mma16(sacc[0], aQ[ks], bK[ks]);
                    mma16(sacc[1], aQ[ks], bK[ks] + 2);
                }
                #pragma unroll
                for (int nt = 0; nt < 2; nt++) {
                    int cb = nt * 8 + 2 * tig;
                    if (cb >= NJ)     { sacc[nt][0] = -1e30f; sacc[nt][2] = -1e30f; }
                    if (cb + 1 >= NJ) { sacc[nt][1] = -1e30f; sacc[nt][3] = -1e30f; }
                }

                float m0 = fmaxf(fmaxf(sacc[0][0], sacc[0][1]), fmaxf(sacc[1][0], sacc[1][1]));
                float m1 = fmaxf(fmaxf(sacc[0][2], sacc[0][3]), fmaxf(sacc[1][2], sacc[1][3]));
                m0 = fmaxf(m0, __shfl_xor_sync(0xFFFFFFFFu, m0, 1));
                m0 = fmaxf(m0, __shfl_xor_sync(0xFFFFFFFFu, m0, 2));
                m1 = fmaxf(m1, __shfl_xor_sync(0xFFFFFFFFu, m1, 1));
                m1 = fmaxf(m1, __shfl_xor_sync(0xFFFFFFFFu, m1, 2));

                float e00 = __expf(sacc[0][0] - m0), e01 = __expf(sacc[0][1] - m0);
                float e10 = __expf(sacc[1][0] - m0), e11 = __expf(sacc[1][1] - m0);
                float f00 = __expf(sacc[0][2] - m1), f01 = __expf(sacc[0][3] - m1);
                float f10 = __expf(sacc[1][2] - m1), f11 = __expf(sacc[1][3] - m1);

                float s0 = e00 + e01 + e10 + e11;
                float s1 = f00 + f01 + f10 + f11;
                s0 += __shfl_xor_sync(0xFFFFFFFFu, s0, 1);
                s0 += __shfl_xor_sync(0xFFFFFFFFu, s0, 2);
                s1 += __shfl_xor_sync(0xFFFFFFFFu, s1, 1);
                s1 += __shfl_xor_sync(0xFFFFFFFFu, s1, 2);
                float i0 = 1.0f / s0, i1 = 1.0f / s1;

                uint32_t pa[4];
                pa[0] = h2u(__floats2half2_rn(e00 * i0, e01 * i0));
                pa[1] = h2u(__floats2half2_rn(f00 * i1, f01 * i1));
                pa[2] = h2u(__floats2half2_rn(e10 * i0, e11 * i0));
                pa[3] = h2u(__floats2half2_rn(f10 * i1, f11 * i1));

                uint32_t vb[2][4];
                {
                    uint32_t ad = hb + (uint32_t)((lane & 15) * QSTR) * 2
                                + 128 + ((lane >> 4) * 16);
                    ldsm_x4t(vb[0], ad);
                    ldsm_x4t(vb[1], ad + 32);
                }
                float oacc[4][4];
                #pragma unroll
                for (int j = 0; j < 4; j++)
                    #pragma unroll
                    for (int r = 0; r < 4; r++) oacc[j][r] = 0.0f;
                mma16(oacc[0], pa, vb[0]);
                mma16(oacc[1], pa, vb[0] + 2);
                mma16(oacc[2], pa, vb[1]);
                mma16(oacc[3], pa, vb[1] + 2);

                int hcol = (2 * p + hh) * HD;
                __half* d0 = AOh + (w * NJ + gid) * TSTR + hcol + 2 * tig;
                #pragma unroll
                for (int j = 0; j < 4; j++)
                    *(__half2*)(d0 + j * 8) = __floats2half2_rn(oacc[j][0], oacc[j][1]);
                int r1 = gid + 8;
                if (r1 < NJ) {
                    __half* d1 = AOh + (w * NJ + r1) * TSTR + hcol + 2 * tig;
                    #pragma unroll
                    for (int j = 0; j < 4; j++)
                        *(__half2*)(d1 + j * 8) = __floats2half2_rn(oacc[j][2], oacc[j][3]);
                }
            }
        } else if (p == 1) {
            // warps 8..11: stage Wo rows 0..95 (16 chunks/row) into the dead X region
            int t2 = tid - 256;                     // 0..127
            #pragma unroll
            for (int j = 0; j < 12; j++) {
                int i = t2 + j * 128;               // < 1536
                int row = i >> 4, ch = (i & 15) * 8;
                cpa16(sbX + (uint32_t)(row * TSTR) * 2 + ch * 2, gWo + row * DM + ch);
            }
            cp_commit();
            cp_wait0();
        }
        __syncthreads();   // QKV reads done (p0) / AO+Wo0-95 ready (p1)

        if (p == 0) {
            // stage W pass 1 (heads 2,3) via cp.async
            #pragma unroll
            for (int j = 0; j < 8; j++) {
                int i = tid + j * THREADS;          // < 3072
                int row = i >> 4, c = (i & 15) * 8;
                int hh  = row >= 96;
                int sub = (row - hh * 96) >> 5;
                cpa16(sbW + (uint32_t)(row * TSTR) * 2 + c * 2,
                      gWqkv + sub * 16384 + ((2 + hh) * HD + (row & 31)) * DM + c);
            }
            cp_commit();
            cp_wait0();
            __syncthreads();
        }
    }

    // ---- stage Wo rows 96..127 (16 chunks/row) into W region ----
    #pragma unroll
    for (int j = 0; j < 2; j++) {
        int i = tid + j * THREADS;
        if (i < 512) {
            int row = i >> 4, ch = (i & 15) * 8;    // row 0..31 -> Wo row 96+row
            cpa16(sbW + (uint32_t)(row * TSTR) * 2 + ch * 2, gWo + (96 + row) * DM + ch);
        }
    }
    cp_commit();
    cp_wait0();
    __syncthreads();

    // ===== final GEMM (12 warps, fm3 x fn4): Y(96x128) = AO @ Wo^T =====
    {
        const int fm = warp >> 2, fn = warp & 3;    // fm 0..2 (32 rows), fn 0..3 (32 cols)
        uint32_t faddr[2], fbaddr[2];
        #pragma unroll
        for (int i = 0; i < 2; i++)
            faddr[i] = sbAO + (uint32_t)((fm * 32 + i * 16 + (lane & 15)) * TSTR) * 2
                            + ((lane >> 4) * 16);
        #pragma unroll
        for (int j = 0; j < 2; j++) {
            int row = fn * 32 + j * 16 + (lane & 7) + ((lane >> 4) * 8);
            uint32_t base = (fn < 3) ? (sbX + (uint32_t)(row * TSTR) * 2)
                                     : (sbW + (uint32_t)((row - 96) * TSTR) * 2);
            fbaddr[j] = base + (((lane >> 3) & 1) * 16);
        }

        float y[2][4][4];
        #pragma unroll
        for (int i = 0; i < 2; i++)
            #pragma unroll
            for (int j = 0; j < 4; j++)
                #pragma unroll
                for (int r = 0; r < 4; r++) y[i][j][r] = 0.0f;

        #pragma unroll
        for (int ks = 0; ks < 8; ks++) {
            uint32_t a[2][4], b[2][4];
            #pragma unroll
            for (int i = 0; i < 2; i++) ldsm_x4(a[i], faddr[i] + ks * 32);
            #pragma unroll
            for (int j = 0; j < 2; j++) ldsm_x4(b[j], fbaddr[j] + ks * 32);
            #pragma unroll
            for (int i = 0; i < 2; i++)
                #pragma unroll
                for (int j = 0; j < 2; j++) {
                    mma16(y[i][2*j],   a[i], b[j]);
                    mma16(y[i][2*j+1], a[i], b[j] + 2);
                }
        }

        #pragma unroll
        for (int i = 0; i < 2; i++) {
            int row = fm * 32 + i * 16 + gid;
            #pragma unroll
            for (int j = 0; j < 4; j++) {
                int col = fn * 32 + j * 8 + 2 * tig;
                float b0 = bos[col], b1 = bos[col + 1];
                size_t base = ((size_t)cta * MR + row) * DM + col;
                *(float2*)(out + base)          = make_float2(y[i][j][0] + b0, y[i][j][1] + b1);
                *(float2*)(out + base + 8 * DM) = make_float2(y[i][j][2] + b0, y[i][j][3] + b1);
            }
        }
    }
}

extern "C" void kernel_launch(void* const* d_in, const int* in_sizes, int n_in,
                              void* d_out, int out_size) {
    const float* x   = (const float*)d_in[0];
    const float* vis = (const float*)d_in[1];
    const float* Wq  = (const float*)d_in[2];
    const float* bq  = (const float*)d_in[3];
    const float* Wk  = (const float*)d_in[4];
    const float* bk  = (const float*)d_in[5];
    const float* Wv  = (const float*)d_in[6];
    const float* bv  = (const float*)d_in[7];
    const float* Wo  = (const float*)d_in[8];
    const float* bo  = (const float*)d_in[9];
    const float* bsc = (const float*)d_in[10];
    const float* adj = (const float*)d_in[11];
    float* out = (float*)d_out;

    const int B = in_sizes[0] / (NJ * DM);      // 16384
    const int grid = B / TB;                    // 2048

    static bool attr_set = false;
    if (!attr_set) {
        cudaFuncSetAttribute(cross_joint_attn_kernel,
                             cudaFuncAttributeMaxDynamicSharedMemorySize, SMEM_BYTES);
        attr_set = true;
    }
    convert_weights<<<16, 256>>>(Wq, Wk, Wv, Wo);
    cross_joint_attn_kernel<<<grid, THREADS, SMEM_BYTES>>>(
        x, vis, bq, bk, bv, bo, bsc, adj, out);
}